// round 5
// baseline (speedup 1.0000x reference)
#include <cuda_runtime.h>
#include <math.h>

#define TD    100
#define SPAD  128     // padded time dim (K of phase 1)
#define DLAT  64
#define DHID  128
#define NPG   64
#define KSZ   25
#define GQ    512
#define BT    256

// Device scratch (no runtime allocations)
__device__ float g_Weff2[4 * 2048];          // 4 chunk-images [64][32] swizzled, [c][s]
__device__ float g_Wcat2[4 * 4096];          // 4 chunk-images [128][32] swizzled, [j][c]
__device__ float g_beff[DLAT];
__device__ float g_Adj[GQ * NPG * NPG];      // [g][dst][src] counts
__device__ float g_Gsum[DHID];
__device__ float g_Gsq[DHID];
__device__ float g_S1[GQ * DHID];
__device__ float g_S2[GQ * DHID];

// packed f32x2 helpers
__device__ __forceinline__ void fma2(unsigned long long& d, unsigned long long a, unsigned long long b) {
    asm("fma.rn.f32x2 %0, %1, %2, %0;" : "+l"(d) : "l"(a), "l"(b));
}
__device__ __forceinline__ float lo32(unsigned long long v) { return __uint_as_float((unsigned)v); }
__device__ __forceinline__ float hi32(unsigned long long v) { return __uint_as_float((unsigned)(v >> 32)); }

// ---------------------------------------------------------------------------
// Kernel 0: prep — swizzled weight images, beff, zero accums + g_Adj
// Swizzle: groups of 4 floats rotated within a 32 (or 64) window by row id.
// ---------------------------------------------------------------------------
__global__ void prep_kernel(const float* __restrict__ conv_w, const float* __restrict__ conv_b,
                            const float* __restrict__ fc1_w, const float* __restrict__ fc1_b,
                            const float* __restrict__ rel_w, const float* __restrict__ root_w) {
    const int tid = blockIdx.x * blockDim.x + threadIdx.x;
    const int nth = gridDim.x * blockDim.x;
    if (blockIdx.x == 0) {
        int t = threadIdx.x;
        if (t < DHID) { g_Gsum[t] = 0.f; g_Gsq[t] = 0.f; }
        if (t < DLAT) {
            float sf = 0.f;
            for (int i = 0; i < TD; i++) sf += fc1_w[i];
            g_beff[t] = conv_b[t] * sf + fc1_b[0];
        }
    }
    // Weff image: logical [c][s], s padded to 128, zero pad
    for (int idx = tid; idx < DLAT * SPAD; idx += nth) {
        int c = idx >> 7, s = idx & 127;
        float w = 0.f;
        if (s < TD) {
            #pragma unroll
            for (int k = 0; k < KSZ; k++) {
                int tt = s + (KSZ / 2) - k;
                if (tt >= 0 && tt < TD) w += conv_w[c * KSZ + k] * fc1_w[tt];
            }
        }
        int kc = s >> 5, sl = s & 31;
        int addr = kc * 2048 + c * 32 + (((sl & ~3) + 4 * ((c >> 2) & 7)) & 31) + (sl & 3);
        g_Weff2[addr] = w;
    }
    // Wcat image: logical [j][c], c = 0..63 rel, 64..127 root
    for (int idx = tid; idx < DHID * DHID; idx += nth) {
        int j = idx >> 7, c = idx & 127;
        float w = (c < DLAT) ? rel_w[j * DLAT + c] : root_w[j * DLAT + (c - DLAT)];
        int q = c >> 5, cl = c & 31;
        int addr = q * 4096 + j * 32 + (((cl & ~3) + 4 * ((j >> 3) & 7)) & 31) + (cl & 3);
        g_Wcat2[addr] = w;
    }
    float4 z = make_float4(0.f, 0.f, 0.f, 0.f);
    float4* A4 = (float4*)g_Adj;
    for (int idx = tid; idx < (GQ * NPG * NPG) / 4; idx += nth) A4[idx] = z;
}

// ---------------------------------------------------------------------------
// Kernel 1: coalesced edge read -> atomic count into g_Adj[g][dst][src]
// ---------------------------------------------------------------------------
__global__ void adj_build(const int* __restrict__ ei, int Etot) {
    const int tid = blockIdx.x * blockDim.x + threadIdx.x;
    const int nth = gridDim.x * blockDim.x;
    for (int e = tid; e < Etot; e += nth) {
        int s = ei[e] & (NPG - 1);
        int d = ei[Etot + e] & (NPG - 1);
        int g = e & (GQ - 1);
        atomicAdd(&g_Adj[(g * NPG + d) * NPG + s], 1.0f);
    }
}

// ---------------------------------------------------------------------------
// Kernel 2: one block per graph, f32x2 K-packed GEMMs.
// smem regions (floats):
//   A [0,8192): xst[64][128] -> {adj[64][64] @A, h2T[64][64] @A+4096}
//               -> wcat ping-pong 2x4096 -> red 2x2048 @A
//   B [8192,12288): weff ping-pong 2x2048 -> agg[64][64]
//   C [12288,16384): h2n[64][64]
// ---------------------------------------------------------------------------
extern __shared__ float sm[];

__global__ void __launch_bounds__(BT)
graph_kernel(const float* __restrict__ x, const float* __restrict__ rel_b) {
    const int g = blockIdx.x;
    const int t = threadIdx.x;
    const int a = t >> 4;        // 0..15
    const int b = t & 15;        // 0..15
    const int swb = 4 * (b & 7); // swizzle rotation for this thread's columns

    float* A = sm;
    float* B = sm + 8192;
    float* C = sm + 12288;

    // ---- stage x -> xst[i][128] (zero pad s>=100), weff chunk0 -> B ----
    {
        const float* xg = x + (size_t)g * NPG * TD;
        #pragma unroll
        for (int r = 0; r < 32; r++) {
            int idx = t + BT * r;
            int i = idx >> 7, s = idx & 127;
            A[idx] = (s < TD) ? xg[i * TD + s] : 0.f;
        }
        float pre[8];
        #pragma unroll
        for (int r = 0; r < 8; r++) pre[r] = g_Weff2[t + BT * r];
        #pragma unroll
        for (int r = 0; r < 8; r++) B[t + BT * r] = pre[r];
    }
    __syncthreads();

    // ---- Phase 1: h2[i][c] = sum_s x[i][s] * Weff[c][s] (K-packed) ----
    unsigned long long acc1[4][4] = {};
    for (int k = 0; k < 4; k++) {
        const float* cur = B + (k & 1) * 2048;
        float pre[8];
        if (k < 3) {
            #pragma unroll
            for (int r = 0; r < 8; r++) pre[r] = g_Weff2[(k + 1) * 2048 + t + BT * r];
        }
        #pragma unroll
        for (int s4 = 0; s4 < 32; s4 += 4) {
            ulonglong2 xu[4], wu[4];
            #pragma unroll
            for (int ii = 0; ii < 4; ii++)
                xu[ii] = *(const ulonglong2*)&A[((4 * a + ii) << 7) + (k << 5) + s4];
            #pragma unroll
            for (int jj = 0; jj < 4; jj++)
                wu[jj] = *(const ulonglong2*)&cur[(4 * b + jj) * 32 + ((s4 + swb) & 31)];
            #pragma unroll
            for (int ii = 0; ii < 4; ii++)
                #pragma unroll
                for (int jj = 0; jj < 4; jj++) {
                    fma2(acc1[ii][jj], xu[ii].x, wu[jj].x);
                    fma2(acc1[ii][jj], xu[ii].y, wu[jj].y);
                }
        }
        if (k < 3) {
            float* nxt = B + ((k + 1) & 1) * 2048;
            #pragma unroll
            for (int r = 0; r < 8; r++) nxt[t + BT * r] = pre[r];
            __syncthreads();
        }
    }
    // epilogue: reduce pairs + bias
    float h2r[4][4];
    {
        float4 bv = *(const float4*)&g_beff[4 * b];
        float br[4] = {bv.x, bv.y, bv.z, bv.w};
        #pragma unroll
        for (int ii = 0; ii < 4; ii++)
            #pragma unroll
            for (int jj = 0; jj < 4; jj++)
                h2r[ii][jj] = lo32(acc1[ii][jj]) + hi32(acc1[ii][jj]) + br[jj];
    }
    __syncthreads();   // all phase-1 reads of A/B done

    // ---- store h2n [i][c] (C), h2T [c][i] swizzled (A+4096), stage adj (A) ----
    #pragma unroll
    for (int ii = 0; ii < 4; ii++)
        *(float4*)&C[(4 * a + ii) * 64 + 4 * b] =
            make_float4(h2r[ii][0], h2r[ii][1], h2r[ii][2], h2r[ii][3]);
    #pragma unroll
    for (int jj = 0; jj < 4; jj++)
        *(float4*)&A[4096 + (4 * b + jj) * 64 + ((4 * a + swb) & 63)] =
            make_float4(h2r[0][jj], h2r[1][jj], h2r[2][jj], h2r[3][jj]);
    {
        const float4* Ag4 = (const float4*)(g_Adj + (size_t)g * NPG * NPG);
        float4* A4 = (float4*)A;
        #pragma unroll
        for (int r = 0; r < 4; r++) A4[t + BT * r] = Ag4[t + BT * r];
    }
    __syncthreads();

    // ---- Phase 2: agg[d][c] = sum_s adj[d][s] * h2T[c][s] (K-packed) ----
    unsigned long long acc2[4][4] = {};
    float pre3[16];
    #pragma unroll
    for (int r = 0; r < 16; r++) pre3[r] = g_Wcat2[t + BT * r];   // prefetch wcat chunk0
    #pragma unroll
    for (int s4 = 0; s4 < 64; s4 += 4) {
        ulonglong2 au[4], hu[4];
        #pragma unroll
        for (int ii = 0; ii < 4; ii++)
            au[ii] = *(const ulonglong2*)&A[((4 * a + ii) << 6) + s4];
        #pragma unroll
        for (int jj = 0; jj < 4; jj++)
            hu[jj] = *(const ulonglong2*)&A[4096 + ((4 * b + jj) << 6) + ((s4 + swb) & 63)];
        #pragma unroll
        for (int ii = 0; ii < 4; ii++)
            #pragma unroll
            for (int jj = 0; jj < 4; jj++) {
                fma2(acc2[ii][jj], au[ii].x, hu[jj].x);
                fma2(acc2[ii][jj], au[ii].y, hu[jj].y);
            }
    }
    // store agg [d][c] -> B
    #pragma unroll
    for (int ii = 0; ii < 4; ii++)
        *(float4*)&B[(4 * a + ii) * 64 + 4 * b] =
            make_float4(lo32(acc2[ii][0]) + hi32(acc2[ii][0]),
                        lo32(acc2[ii][1]) + hi32(acc2[ii][1]),
                        lo32(acc2[ii][2]) + hi32(acc2[ii][2]),
                        lo32(acc2[ii][3]) + hi32(acc2[ii][3]));
    __syncthreads();   // agg visible; A free

    // stage wcat chunk0
    #pragma unroll
    for (int r = 0; r < 16; r++) A[t + BT * r] = pre3[r];
    __syncthreads();

    // ---- Phase 3: out[i][j] = sum_c M[i][c] * Wcat[j][c] (K-packed) ----
    unsigned long long acc3[4][8] = {};
    for (int q = 0; q < 4; q++) {
        const float* cur = A + (q & 1) * 4096;
        float pre[16];
        if (q < 3) {
            #pragma unroll
            for (int r = 0; r < 16; r++) pre[r] = g_Wcat2[(q + 1) * 4096 + t + BT * r];
        }
        const float* msrc = (q < 2) ? B : C;
        const int coff = (q & 1) * 32;
        #pragma unroll
        for (int c4 = 0; c4 < 32; c4 += 4) {
            ulonglong2 mu[4], wu[8];
            #pragma unroll
            for (int ii = 0; ii < 4; ii++)
                mu[ii] = *(const ulonglong2*)&msrc[((4 * a + ii) << 6) + coff + c4];
            #pragma unroll
            for (int jj = 0; jj < 8; jj++)
                wu[jj] = *(const ulonglong2*)&cur[(8 * b + jj) * 32 + ((c4 + swb) & 31)];
            #pragma unroll
            for (int ii = 0; ii < 4; ii++)
                #pragma unroll
                for (int jj = 0; jj < 8; jj++) {
                    fma2(acc3[ii][jj], mu[ii].x, wu[jj].x);
                    fma2(acc3[ii][jj], mu[ii].y, wu[jj].y);
                }
        }
        if (q < 3) {
            float* nxt = A + ((q + 1) & 1) * 4096;
            #pragma unroll
            for (int r = 0; r < 16; r++) nxt[t + BT * r] = pre[r];
            __syncthreads();
        }
    }

    // epilogue: bias + per-thread moments over 4 rows, for 8 j's
    float4 rb0 = *(const float4*)&rel_b[8 * b];
    float4 rb1 = *(const float4*)&rel_b[8 * b + 4];
    float rbv[8] = {rb0.x, rb0.y, rb0.z, rb0.w, rb1.x, rb1.y, rb1.z, rb1.w};
    float s1p[8], s2p[8];
    #pragma unroll
    for (int jj = 0; jj < 8; jj++) {
        float s1 = 0.f, s2 = 0.f;
        #pragma unroll
        for (int ii = 0; ii < 4; ii++) {
            float v = lo32(acc3[ii][jj]) + hi32(acc3[ii][jj]) + rbv[jj];
            s1 += v; s2 += v * v;
        }
        s1p[jj] = s1; s2p[jj] = s2;
    }
    // block reduce over 16 i-groups; red in A[0,4096) (chunk3 lives at A+4096)
    float* red = A;
    #pragma unroll
    for (int jj = 0; jj < 8; jj++) {
        red[a * DHID + 8 * b + jj]        = s1p[jj];
        red[2048 + a * DHID + 8 * b + jj] = s2p[jj];
    }
    __syncthreads();
    if (t < DHID) {
        float S1 = 0.f, S2 = 0.f;
        #pragma unroll
        for (int qq = 0; qq < 16; qq++) {
            S1 += red[qq * DHID + t];
            S2 += red[2048 + qq * DHID + t];
        }
        g_S1[g * DHID + t] = S1;
        g_S2[g * DHID + t] = S2;
        atomicAdd(&g_Gsum[t], S1);
        atomicAdd(&g_Gsq[t], S2);
    }
}

// ---------------------------------------------------------------------------
// Kernel 3: BN stats -> pooled moments -> log -> fc2 -> sigmoid (2 graphs/CTA)
// ---------------------------------------------------------------------------
__global__ void final_kernel(const float* __restrict__ bn_g, const float* __restrict__ bn_b,
                             const float* __restrict__ fc2_w, const float* __restrict__ fc2_b,
                             float* __restrict__ out, float invN) {
    int t = threadIdx.x;
    int h = t >> 7;                       // sub-block (graph within CTA)
    int g = blockIdx.x * 2 + h;
    int j = t & 127;
    float mu  = g_Gsum[j] * invN;
    float var = g_Gsq[j] * invN - mu * mu;
    float aa  = bn_g[j] * rsqrtf(var + 1e-5f);
    float cc  = bn_b[j] - aa * mu;
    float s1  = g_S1[g * DHID + j];
    float s2  = g_S2[g * DHID + j];
    float pooled = (aa * aa * s2 + 2.f * aa * cc * s1) * (1.f / 64.f) + cc * cc;
    float pl = logf(fmaxf(pooled, 1e-6f));
    float p0 = pl * fc2_w[j];
    float p1 = pl * fc2_w[DHID + j];
    float p2 = pl * fc2_w[2 * DHID + j];
    #pragma unroll
    for (int off = 16; off > 0; off >>= 1) {
        p0 += __shfl_down_sync(0xffffffffu, p0, off);
        p1 += __shfl_down_sync(0xffffffffu, p1, off);
        p2 += __shfl_down_sync(0xffffffffu, p2, off);
    }
    __shared__ float r[24];
    if ((t & 31) == 0) {
        int w = t >> 5;                   // 0..7
        r[w * 3 + 0] = p0; r[w * 3 + 1] = p1; r[w * 3 + 2] = p2;
    }
    __syncthreads();
    if (j < 3) {
        int base = h * 12;
        float v = r[base + j] + r[base + 3 + j] + r[base + 6 + j] + r[base + 9 + j] + fc2_b[j];
        out[g * 3 + j] = 1.f / (1.f + expf(-v));
    }
}

// ---------------------------------------------------------------------------
extern "C" void kernel_launch(void* const* d_in, const int* in_sizes, int n_in,
                              void* d_out, int out_size) {
    const float* x      = (const float*)d_in[0];
    const int*   ei     = (const int*)d_in[1];     // int32 (JAX x64 disabled)
    const float* conv_w = (const float*)d_in[3];
    const float* conv_b = (const float*)d_in[4];
    const float* fc1_w  = (const float*)d_in[5];
    const float* fc1_b  = (const float*)d_in[6];
    const float* rel_w  = (const float*)d_in[7];
    const float* rel_b  = (const float*)d_in[8];
    const float* root_w = (const float*)d_in[9];
    const float* bn_g   = (const float*)d_in[10];
    const float* bn_b   = (const float*)d_in[11];
    const float* fc2_w  = (const float*)d_in[12];
    const float* fc2_b  = (const float*)d_in[13];
    float* out = (float*)d_out;

    const int Ntot = in_sizes[0] / TD;     // 32768
    const int G    = Ntot / NPG;           // 512
    const int Etot = in_sizes[1] / 2;      // 1048576

    const int smem_bytes = 16384 * 4;      // 64KB
    cudaFuncSetAttribute(graph_kernel, cudaFuncAttributeMaxDynamicSharedMemorySize, smem_bytes);

    prep_kernel<<<256, BT>>>(conv_w, conv_b, fc1_w, fc1_b, rel_w, root_w);
    adj_build<<<2048, BT>>>(ei, Etot);
    graph_kernel<<<G, BT, smem_bytes>>>(x, rel_b);
    final_kernel<<<G / 2, BT>>>(bn_g, bn_b, fc2_w, fc2_b, out, 1.0f / (float)Ntot);
}

// round 6
// speedup vs baseline: 1.1372x; 1.1372x over previous
#include <cuda_runtime.h>
#include <math.h>

#define TD    100
#define DLAT  64
#define DHID  128
#define NPG   64
#define KSZ   25
#define GQ    512
#define BT    256

// Device scratch (no runtime allocations)
__device__ float g_Weff2[4 * 2048];   // [k][c 64][s 32], 4-float groups rotated by (c>>2)&7
__device__ float g_Wcat2[4 * 4096];   // [q][cc 32][j 128] plain transpose
__device__ float g_beff[DLAT];
__device__ float g_Adj[GQ * NPG * NPG]; // [g][dst][src]
__device__ float g_Gsum[DHID];
__device__ float g_Gsq[DHID];
__device__ float g_S1[GQ * DHID];
__device__ float g_S2[GQ * DHID];

typedef unsigned long long ull;
__device__ __forceinline__ void fma2(ull& d, ull a, ull b) {
    asm("fma.rn.f32x2 %0, %1, %2, %0;" : "+l"(d) : "l"(a), "l"(b));
}
__device__ __forceinline__ ull dup2(float v) {
    ull r; asm("mov.b64 %0, {%1, %1};" : "=l"(r) : "f"(v)); return r;
}
__device__ __forceinline__ ull add2(ull a, ull b) {
    ull r; asm("add.rn.f32x2 %0, %1, %2;" : "=l"(r) : "l"(a), "l"(b)); return r;
}
__device__ __forceinline__ float lo32(ull v) { return __uint_as_float((unsigned)v); }
__device__ __forceinline__ float hi32(ull v) { return __uint_as_float((unsigned)(v >> 32)); }

// ---------------------------------------------------------------------------
// Kernel 0: prep — weight images, beff, zero accumulators + g_Adj
// ---------------------------------------------------------------------------
__global__ void prep_kernel(const float* __restrict__ conv_w, const float* __restrict__ conv_b,
                            const float* __restrict__ fc1_w, const float* __restrict__ fc1_b,
                            const float* __restrict__ rel_w, const float* __restrict__ root_w) {
    const int tid = blockIdx.x * blockDim.x + threadIdx.x;
    const int nth = gridDim.x * blockDim.x;
    if (blockIdx.x == 0) {
        int t = threadIdx.x;
        if (t < DHID) { g_Gsum[t] = 0.f; g_Gsq[t] = 0.f; }
        if (t < DLAT) {
            float sf = 0.f;
            for (int i = 0; i < TD; i++) sf += fc1_w[i];
            g_beff[t] = conv_b[t] * sf + fc1_b[0];
        }
    }
    // Weff image: chunk k=(s>>5): [c][32], 4-float groups rotated by (c>>2)&7
    for (int idx = tid; idx < DLAT * 128; idx += nth) {
        int c = idx >> 7, s = idx & 127;
        float w = 0.f;
        if (s < TD) {
            #pragma unroll
            for (int k = 0; k < KSZ; k++) {
                int tt = s + (KSZ / 2) - k;
                if (tt >= 0 && tt < TD) w += conv_w[c * KSZ + k] * fc1_w[tt];
            }
        }
        int kc = s >> 5, sl = s & 31;
        int addr = kc * 2048 + c * 32 + (((sl & ~3) + 4 * ((c >> 2) & 7)) & 31) + (sl & 3);
        g_Weff2[addr] = w;
    }
    // Wcat image: [q=c>>5][cc=c&31][j] (plain transpose)
    for (int idx = tid; idx < DHID * DHID; idx += nth) {
        int j = idx >> 7, c = idx & 127;
        float w = (c < DLAT) ? rel_w[j * DLAT + c] : root_w[j * DLAT + (c - DLAT)];
        g_Wcat2[(c >> 5) * 4096 + (c & 31) * 128 + j] = w;
    }
    float4 z = make_float4(0.f, 0.f, 0.f, 0.f);
    float4* A4 = (float4*)g_Adj;
    for (int idx = tid; idx < (GQ * NPG * NPG) / 4; idx += nth) A4[idx] = z;
}

// ---------------------------------------------------------------------------
// Kernel 1: coalesced edge read -> atomic count into g_Adj[g][dst][src]
// ---------------------------------------------------------------------------
__global__ void adj_build(const int* __restrict__ ei, int Etot) {
    const int tid = blockIdx.x * blockDim.x + threadIdx.x;
    const int nth = gridDim.x * blockDim.x;
    for (int e = tid; e < Etot; e += nth) {
        int s = ei[e] & (NPG - 1);
        int d = ei[Etot + e] & (NPG - 1);
        int g = e & (GQ - 1);
        atomicAdd(&g_Adj[(g * NPG + d) * NPG + s], 1.0f);
    }
}

// ---------------------------------------------------------------------------
// Kernel 2: 2 graphs per CTA (256 CTAs). smem 24576 floats (96KB):
//   WEF [0,8192):      Weff all 4 chunks -> Wcat ping-pong 2x4096 -> RED in buf0
//   XB  [8192,16384):  X ping-pong 2x4096 -> ADJ [2][64][64] -> AGG [128][64]
//   H2N [16384,24576): h2 [128 rows][64]
// ---------------------------------------------------------------------------
extern __shared__ float sm[];

#define P1_STEP(Xb, Wk, s4) {                                                  \
    ulonglong2 xu[8], wu[4];                                                   \
    _Pragma("unroll")                                                          \
    for (int ii = 0; ii < 8; ii++)                                             \
        xu[ii] = *(const ulonglong2*)&(Xb)[(8 * a + ii) * 32 + (s4)];          \
    _Pragma("unroll")                                                          \
    for (int jj = 0; jj < 4; jj++)                                             \
        wu[jj] = *(const ulonglong2*)&(Wk)[(4 * b + jj) * 32 + (((s4) + swb) & 31)]; \
    _Pragma("unroll")                                                          \
    for (int ii = 0; ii < 8; ii++)                                             \
        _Pragma("unroll")                                                      \
        for (int jj = 0; jj < 4; jj++) {                                       \
            fma2(acc1[ii][jj], xu[ii].x, wu[jj].x);                            \
            fma2(acc1[ii][jj], xu[ii].y, wu[jj].y);                            \
        }                                                                      \
}

__global__ void __launch_bounds__(BT, 2)
graph_kernel(const float* __restrict__ x, const float* __restrict__ rel_b) {
    const int bid = blockIdx.x;        // graphs 2*bid, 2*bid+1
    const int t = threadIdx.x;
    const int a = t >> 4;              // 0..15 -> rows 8a..8a+7 (global 0..127)
    const int b = t & 15;
    const int swb = 4 * (b & 7);
    const int gg = a >> 3;             // graph-in-CTA of this thread's rows

    float* WEF = sm;
    float* XB  = sm + 8192;
    float* H2N = sm + 16384;

    const float* xg = x + (size_t)bid * 128 * TD;

    // ---- stage Weff (all) + X chunk 0 ----
    #pragma unroll
    for (int q = 0; q < 8; q++)
        ((float4*)WEF)[t + BT * q] = ((const float4*)g_Weff2)[t + BT * q];
    #pragma unroll
    for (int q = 0; q < 4; q++) {
        int i4 = t + BT * q;
        int r = i4 >> 3, s0 = (i4 & 7) * 4;
        *(float4*)&XB[r * 32 + s0] = *(const float4*)&xg[r * TD + s0];
    }
    __syncthreads();

    // ---- Phase 1: h2[r][c] = sum_s x[r][s]*Weff[c][s], K-packed 8x4 ----
    ull acc1[8][4] = {};
    for (int k = 0; k < 3; k++) {
        const float* Xb = XB + (k & 1) * 4096;
        const float* Wk = WEF + k * 2048;
        float4 xn[4];
        #pragma unroll
        for (int q = 0; q < 4; q++) {
            int i4 = t + BT * q;
            int r = i4 >> 3, s0 = (k + 1) * 32 + (i4 & 7) * 4;
            xn[q] = (s0 < TD) ? *(const float4*)&xg[r * TD + s0]
                              : make_float4(0.f, 0.f, 0.f, 0.f);
        }
        #pragma unroll
        for (int si = 0; si < 8; si++) { P1_STEP(Xb, Wk, si * 4); }
        float* Xn = XB + ((k + 1) & 1) * 4096;
        #pragma unroll
        for (int q = 0; q < 4; q++) {
            int i4 = t + BT * q;
            int r = i4 >> 3, s0 = (i4 & 7) * 4;
            *(float4*)&Xn[r * 32 + s0] = xn[q];
        }
        __syncthreads();
    }
    // chunk 3: only s=96..99 valid -> one step; also prefetch ADJ
    float4 adjv[8];
    {
        const float4* Ag4 = (const float4*)(g_Adj + (size_t)bid * 8192);
        #pragma unroll
        for (int q = 0; q < 8; q++) adjv[q] = Ag4[t + BT * q];
        const float* Xb = XB + 4096;     // chunk 3 buffer (k=3 odd)
        const float* Wk = WEF + 3 * 2048;
        P1_STEP(Xb, Wk, 0);
    }

    // ---- epilogue P1: h2 -> H2N ----
    {
        float4 bv = *(const float4*)&g_beff[4 * b];
        float br[4] = {bv.x, bv.y, bv.z, bv.w};
        #pragma unroll
        for (int ii = 0; ii < 8; ii++) {
            float4 o;
            o.x = lo32(acc1[ii][0]) + hi32(acc1[ii][0]) + br[0];
            o.y = lo32(acc1[ii][1]) + hi32(acc1[ii][1]) + br[1];
            o.z = lo32(acc1[ii][2]) + hi32(acc1[ii][2]) + br[2];
            o.w = lo32(acc1[ii][3]) + hi32(acc1[ii][3]) + br[3];
            *(float4*)&H2N[(8 * a + ii) * 64 + 4 * b] = o;
        }
    }
    __syncthreads();                     // all X reads done
    #pragma unroll
    for (int q = 0; q < 8; q++) ((float4*)XB)[t + BT * q] = adjv[q];  // ADJ
    __syncthreads();                     // ADJ + H2N visible

    // ---- Phase 2: agg[d][c] = sum_s adj[d][s]*h2[s][c], N-packed 8x(2 ull) ----
    ull acc2[8][2] = {};
    float wc0[16];
    #pragma unroll
    for (int q = 0; q < 16; q++) wc0[q] = g_Wcat2[t + BT * q];  // prefetch Wcat chunk0
    {
        const float* ADJs = XB + gg * 4096;
        const float* H2g  = H2N + gg * 4096;
        #pragma unroll 4
        for (int si = 0; si < 16; si++) {
            int s4 = si * 4;
            float af[8][4];
            #pragma unroll
            for (int ii = 0; ii < 8; ii++) {
                float4 v = *(const float4*)&ADJs[(8 * (a & 7) + ii) * 64 + s4];
                af[ii][0] = v.x; af[ii][1] = v.y; af[ii][2] = v.z; af[ii][3] = v.w;
            }
            #pragma unroll
            for (int s2 = 0; s2 < 4; s2++) {
                ulonglong2 hv = *(const ulonglong2*)&H2g[(s4 + s2) * 64 + 4 * b];
                #pragma unroll
                for (int ii = 0; ii < 8; ii++) {
                    ull m2 = dup2(af[ii][s2]);
                    fma2(acc2[ii][0], m2, hv.x);
                    fma2(acc2[ii][1], m2, hv.y);
                }
            }
        }
    }
    __syncthreads();                     // ADJ reads done
    #pragma unroll
    for (int ii = 0; ii < 8; ii++)       // AGG overwrites ADJ region (global rows)
        *(float4*)&XB[(8 * a + ii) * 64 + 4 * b] =
            make_float4(lo32(acc2[ii][0]), hi32(acc2[ii][0]),
                        lo32(acc2[ii][1]), hi32(acc2[ii][1]));
    #pragma unroll
    for (int q = 0; q < 16; q++) WEF[t + BT * q] = wc0[q];       // Wcat buf0
    __syncthreads();

    // ---- Phase 3: out[r][j] = sum_c M[r][c]*Wcat[c][j], N-packed 8x(4 ull) ----
    // thread's j pairs: (2b+32s, 2b+1+32s), s=0..3
    ull acc3[8][4] = {};
    for (int q = 0; q < 4; q++) {
        const float* Wq = WEF + (q & 1) * 4096;
        float wn[16];
        if (q < 3) {
            #pragma unroll
            for (int r = 0; r < 16; r++) wn[r] = g_Wcat2[(q + 1) * 4096 + t + BT * r];
        }
        const float* M = (q < 2) ? XB : H2N;
        const int coff = (q & 1) * 32;
        #pragma unroll
        for (int ci = 0; ci < 8; ci++) {
            int c4 = ci * 4;
            float mf[8][4];
            #pragma unroll
            for (int ii = 0; ii < 8; ii++) {
                float4 v = *(const float4*)&M[(8 * a + ii) * 64 + coff + c4];
                mf[ii][0] = v.x; mf[ii][1] = v.y; mf[ii][2] = v.z; mf[ii][3] = v.w;
            }
            #pragma unroll
            for (int c2 = 0; c2 < 4; c2++) {
                ull wv[4];
                #pragma unroll
                for (int s = 0; s < 4; s++)
                    wv[s] = *(const ull*)&Wq[(c4 + c2) * 128 + 2 * b + 32 * s];
                #pragma unroll
                for (int ii = 0; ii < 8; ii++) {
                    ull m2 = dup2(mf[ii][c2]);
                    #pragma unroll
                    for (int s = 0; s < 4; s++) fma2(acc3[ii][s], m2, wv[s]);
                }
            }
        }
        if (q < 3) {
            float* Wn = WEF + ((q + 1) & 1) * 4096;
            #pragma unroll
            for (int r = 0; r < 16; r++) Wn[t + BT * r] = wn[r];
            __syncthreads();
        }
    }

    // ---- epilogue: bias + moments (packed lanes = separate j's) ----
    float* RED = WEF;                    // buf0: free (q=3 reads buf1/AGG/H2N only)
    #pragma unroll
    for (int s = 0; s < 4; s++) {
        ull rb = *(const ull*)&rel_b[2 * b + 32 * s];
        ull sum1 = 0ull, sum2 = 0ull;
        #pragma unroll
        for (int ii = 0; ii < 8; ii++) {
            ull v = add2(acc3[ii][s], rb);
            sum1 = add2(sum1, v);
            fma2(sum2, v, v);
        }
        int base = gg * 1024 + (a & 7) * 128 + 2 * b + 32 * s;
        *(ull*)&RED[base]        = sum1;
        *(ull*)&RED[2048 + base] = sum2;
    }
    __syncthreads();
    {
        int gg2 = t >> 7, j = t & 127;
        float S1 = 0.f, S2 = 0.f;
        #pragma unroll
        for (int ag = 0; ag < 8; ag++) {
            S1 += RED[gg2 * 1024 + ag * 128 + j];
            S2 += RED[2048 + gg2 * 1024 + ag * 128 + j];
        }
        int gl = bid * 2 + gg2;
        g_S1[gl * DHID + j] = S1;
        g_S2[gl * DHID + j] = S2;
        atomicAdd(&g_Gsum[j], S1);
        atomicAdd(&g_Gsq[j], S2);
    }
}

// ---------------------------------------------------------------------------
// Kernel 3: BN stats -> pooled moments -> log -> fc2 -> sigmoid (2 graphs/CTA)
// ---------------------------------------------------------------------------
__global__ void final_kernel(const float* __restrict__ bn_g, const float* __restrict__ bn_b,
                             const float* __restrict__ fc2_w, const float* __restrict__ fc2_b,
                             float* __restrict__ out, float invN) {
    int t = threadIdx.x;
    int h = t >> 7;
    int g = blockIdx.x * 2 + h;
    int j = t & 127;
    float mu  = g_Gsum[j] * invN;
    float var = g_Gsq[j] * invN - mu * mu;
    float aa  = bn_g[j] * rsqrtf(var + 1e-5f);
    float cc  = bn_b[j] - aa * mu;
    float s1  = g_S1[g * DHID + j];
    float s2  = g_S2[g * DHID + j];
    float pooled = (aa * aa * s2 + 2.f * aa * cc * s1) * (1.f / 64.f) + cc * cc;
    float pl = logf(fmaxf(pooled, 1e-6f));
    float p0 = pl * fc2_w[j];
    float p1 = pl * fc2_w[DHID + j];
    float p2 = pl * fc2_w[2 * DHID + j];
    #pragma unroll
    for (int off = 16; off > 0; off >>= 1) {
        p0 += __shfl_down_sync(0xffffffffu, p0, off);
        p1 += __shfl_down_sync(0xffffffffu, p1, off);
        p2 += __shfl_down_sync(0xffffffffu, p2, off);
    }
    __shared__ float r[24];
    if ((t & 31) == 0) {
        int w = t >> 5;
        r[w * 3 + 0] = p0; r[w * 3 + 1] = p1; r[w * 3 + 2] = p2;
    }
    __syncthreads();
    if (j < 3) {
        int base = h * 12;
        float v = r[base + j] + r[base + 3 + j] + r[base + 6 + j] + r[base + 9 + j] + fc2_b[j];
        out[g * 3 + j] = 1.f / (1.f + expf(-v));
    }
}

// ---------------------------------------------------------------------------
extern "C" void kernel_launch(void* const* d_in, const int* in_sizes, int n_in,
                              void* d_out, int out_size) {
    const float* x      = (const float*)d_in[0];
    const int*   ei     = (const int*)d_in[1];     // int32 (JAX x64 disabled)
    const float* conv_w = (const float*)d_in[3];
    const float* conv_b = (const float*)d_in[4];
    const float* fc1_w  = (const float*)d_in[5];
    const float* fc1_b  = (const float*)d_in[6];
    const float* rel_w  = (const float*)d_in[7];
    const float* rel_b  = (const float*)d_in[8];
    const float* root_w = (const float*)d_in[9];
    const float* bn_g   = (const float*)d_in[10];
    const float* bn_b   = (const float*)d_in[11];
    const float* fc2_w  = (const float*)d_in[12];
    const float* fc2_b  = (const float*)d_in[13];
    float* out = (float*)d_out;

    const int Ntot = in_sizes[0] / TD;     // 32768
    const int G    = Ntot / NPG;           // 512
    const int Etot = in_sizes[1] / 2;      // 1048576

    const int smem_bytes = 24576 * 4;      // 96KB
    cudaFuncSetAttribute(graph_kernel, cudaFuncAttributeMaxDynamicSharedMemorySize, smem_bytes);

    prep_kernel<<<256, BT>>>(conv_w, conv_b, fc1_w, fc1_b, rel_w, root_w);
    adj_build<<<2048, BT>>>(ei, Etot);
    graph_kernel<<<G / 2, BT, smem_bytes>>>(x, rel_b);
    final_kernel<<<G / 2, BT>>>(bn_g, bn_b, fc2_w, fc2_b, out, 1.0f / (float)Ntot);
}

// round 7
// speedup vs baseline: 1.3446x; 1.1823x over previous
#include <cuda_runtime.h>
#include <math.h>

#define TD    100
#define DLAT  64
#define DHID  128
#define NPG   64
#define KSZ   25
#define GQ    512
#define BT    256

// Device scratch (no runtime allocations; zero-initialized at module load)
__device__ float g_Weff2[4 * 2048];   // [k][c 64][s 32], 4-float groups rotated by (c>>2)&7
__device__ float g_Wcat2[4 * 4096];   // [q][cc 32][j 128] plain transpose
__device__ float g_beff[DLAT];
__device__ float g_Adj[GQ * NPG * NPG]; // [g][dst][src]; ALWAYS zero at kernel entry
__device__ float g_Gsum[DHID];
__device__ float g_Gsq[DHID];
__device__ float g_S1[GQ * DHID];
__device__ float g_S2[GQ * DHID];

typedef unsigned long long ull;
__device__ __forceinline__ void fma2(ull& d, ull a, ull b) {
    asm("fma.rn.f32x2 %0, %1, %2, %0;" : "+l"(d) : "l"(a), "l"(b));
}
__device__ __forceinline__ ull dup2(float v) {
    ull r; asm("mov.b64 %0, {%1, %1};" : "=l"(r) : "f"(v)); return r;
}
__device__ __forceinline__ ull add2(ull a, ull b) {
    ull r; asm("add.rn.f32x2 %0, %1, %2;" : "=l"(r) : "l"(a), "l"(b)); return r;
}
__device__ __forceinline__ float lo32(ull v) { return __uint_as_float((unsigned)v); }
__device__ __forceinline__ float hi32(ull v) { return __uint_as_float((unsigned)(v >> 32)); }

// ---------------------------------------------------------------------------
// Kernel 0: setup — weight images + beff + Gsum/Gsq zero + edge scatter.
// g_Adj is NOT zeroed here: it is zero at entry (static init on launch 1,
// zero-after-read in graph_kernel thereafter).
// ---------------------------------------------------------------------------
__global__ void setup_kernel(const float* __restrict__ conv_w, const float* __restrict__ conv_b,
                             const float* __restrict__ fc1_w, const float* __restrict__ fc1_b,
                             const float* __restrict__ rel_w, const float* __restrict__ root_w,
                             const int* __restrict__ ei, int Etot) {
    const int tid = blockIdx.x * blockDim.x + threadIdx.x;
    const int nth = gridDim.x * blockDim.x;

    if (blockIdx.x == 0) {
        int t = threadIdx.x;
        if (t < DHID) { g_Gsum[t] = 0.f; g_Gsq[t] = 0.f; }
        if (t < DLAT) {
            float sf = 0.f;
            for (int i = 0; i < TD; i++) sf += fc1_w[i];
            g_beff[t] = conv_b[t] * sf + fc1_b[0];
        }
    }
    // Weff image: chunk k=(s>>5): [c][32], 4-float groups rotated by (c>>2)&7
    for (int idx = tid; idx < DLAT * 128; idx += nth) {
        int c = idx >> 7, s = idx & 127;
        float w = 0.f;
        if (s < TD) {
            #pragma unroll
            for (int k = 0; k < KSZ; k++) {
                int tt = s + (KSZ / 2) - k;
                if (tt >= 0 && tt < TD) w += conv_w[c * KSZ + k] * fc1_w[tt];
            }
        }
        int kc = s >> 5, sl = s & 31;
        int addr = kc * 2048 + c * 32 + (((sl & ~3) + 4 * ((c >> 2) & 7)) & 31) + (sl & 3);
        g_Weff2[addr] = w;
    }
    // Wcat image: [q=c>>5][cc=c&31][j] (plain transpose)
    for (int idx = tid; idx < DHID * DHID; idx += nth) {
        int j = idx >> 7, c = idx & 127;
        float w = (c < DLAT) ? rel_w[j * DLAT + c] : root_w[j * DLAT + (c - DLAT)];
        g_Wcat2[(c >> 5) * 4096 + (c & 31) * 128 + j] = w;
    }
    // Edge scatter: 8 edges per thread via 2x int4 loads, coalesced.
    const int4* src4 = (const int4*)ei;
    const int4* dst4 = (const int4*)(ei + Etot);
    const int nv = Etot >> 3;
    for (int i = tid; i < nv; i += nth) {
        int4 sa = src4[2 * i],     sb = src4[2 * i + 1];
        int4 da = dst4[2 * i],     db = dst4[2 * i + 1];
        int e0 = 8 * i;
        int sv[8] = {sa.x, sa.y, sa.z, sa.w, sb.x, sb.y, sb.z, sb.w};
        int dv[8] = {da.x, da.y, da.z, da.w, db.x, db.y, db.z, db.w};
        #pragma unroll
        for (int k = 0; k < 8; k++) {
            int g = (e0 + k) & (GQ - 1);
            atomicAdd(&g_Adj[(g * NPG + (dv[k] & (NPG - 1))) * NPG + (sv[k] & (NPG - 1))], 1.0f);
        }
    }
}

// ---------------------------------------------------------------------------
// Kernel 1: 2 graphs per CTA (256 CTAs). smem 24576 floats (96KB):
//   WEF [0,8192):      Weff all 4 chunks -> Wcat ping-pong 2x4096 -> RED in buf0
//   XB  [8192,16384):  X ping-pong 2x4096 -> ADJ [2][64][64] -> AGG [128][64]
//   H2N [16384,24576): h2 [128 rows][64]
// ---------------------------------------------------------------------------
extern __shared__ float sm[];

#define P1_STEP(Xb, Wk, s4) {                                                  \
    ulonglong2 xu[8], wu[4];                                                   \
    _Pragma("unroll")                                                          \
    for (int ii = 0; ii < 8; ii++)                                             \
        xu[ii] = *(const ulonglong2*)&(Xb)[(8 * a + ii) * 32 + (s4)];          \
    _Pragma("unroll")                                                          \
    for (int jj = 0; jj < 4; jj++)                                             \
        wu[jj] = *(const ulonglong2*)&(Wk)[(4 * b + jj) * 32 + (((s4) + swb) & 31)]; \
    _Pragma("unroll")                                                          \
    for (int ii = 0; ii < 8; ii++)                                             \
        _Pragma("unroll")                                                      \
        for (int jj = 0; jj < 4; jj++) {                                       \
            fma2(acc1[ii][jj], xu[ii].x, wu[jj].x);                            \
            fma2(acc1[ii][jj], xu[ii].y, wu[jj].y);                            \
        }                                                                      \
}

__global__ void __launch_bounds__(BT, 2)
graph_kernel(const float* __restrict__ x, const float* __restrict__ rel_b) {
    const int bid = blockIdx.x;        // graphs 2*bid, 2*bid+1
    const int t = threadIdx.x;
    const int a = t >> 4;              // 0..15 -> rows 8a..8a+7 (global 0..127)
    const int b = t & 15;
    const int swb = 4 * (b & 7);
    const int gg = a >> 3;             // graph-in-CTA of this thread's rows

    float* WEF = sm;
    float* XB  = sm + 8192;
    float* H2N = sm + 16384;

    const float* xg = x + (size_t)bid * 128 * TD;

    // ---- stage Weff (all) + X chunk 0 ----
    #pragma unroll
    for (int q = 0; q < 8; q++)
        ((float4*)WEF)[t + BT * q] = ((const float4*)g_Weff2)[t + BT * q];
    #pragma unroll
    for (int q = 0; q < 4; q++) {
        int i4 = t + BT * q;
        int r = i4 >> 3, s0 = (i4 & 7) * 4;
        *(float4*)&XB[r * 32 + s0] = *(const float4*)&xg[r * TD + s0];
    }
    __syncthreads();

    // ---- Phase 1: h2[r][c] = sum_s x[r][s]*Weff[c][s], K-packed 8x4 ----
    ull acc1[8][4] = {};
    for (int k = 0; k < 3; k++) {
        const float* Xb = XB + (k & 1) * 4096;
        const float* Wk = WEF + k * 2048;
        float4 xn[4];
        #pragma unroll
        for (int q = 0; q < 4; q++) {
            int i4 = t + BT * q;
            int r = i4 >> 3, s0 = (k + 1) * 32 + (i4 & 7) * 4;
            xn[q] = (s0 < TD) ? *(const float4*)&xg[r * TD + s0]
                              : make_float4(0.f, 0.f, 0.f, 0.f);
        }
        #pragma unroll
        for (int si = 0; si < 8; si++) { P1_STEP(Xb, Wk, si * 4); }
        float* Xn = XB + ((k + 1) & 1) * 4096;
        #pragma unroll
        for (int q = 0; q < 4; q++) {
            int i4 = t + BT * q;
            int r = i4 >> 3, s0 = (i4 & 7) * 4;
            *(float4*)&Xn[r * 32 + s0] = xn[q];
        }
        __syncthreads();
    }
    // chunk 3: only s=96..99 valid -> one step; also prefetch ADJ + zero it
    float4 adjv[8];
    {
        float4* Ag4 = (float4*)(g_Adj + (size_t)bid * 8192);
        #pragma unroll
        for (int q = 0; q < 8; q++) adjv[q] = Ag4[t + BT * q];
        // zero-after-read: keeps g_Adj == 0 for the next launch (replay-safe)
        float4 z = make_float4(0.f, 0.f, 0.f, 0.f);
        #pragma unroll
        for (int q = 0; q < 8; q++) Ag4[t + BT * q] = z;
        const float* Xb = XB + 4096;     // chunk 3 buffer (k=3 odd)
        const float* Wk = WEF + 3 * 2048;
        P1_STEP(Xb, Wk, 0);
    }

    // ---- epilogue P1: h2 -> H2N ----
    {
        float4 bv = *(const float4*)&g_beff[4 * b];
        float br[4] = {bv.x, bv.y, bv.z, bv.w};
        #pragma unroll
        for (int ii = 0; ii < 8; ii++) {
            float4 o;
            o.x = lo32(acc1[ii][0]) + hi32(acc1[ii][0]) + br[0];
            o.y = lo32(acc1[ii][1]) + hi32(acc1[ii][1]) + br[1];
            o.z = lo32(acc1[ii][2]) + hi32(acc1[ii][2]) + br[2];
            o.w = lo32(acc1[ii][3]) + hi32(acc1[ii][3]) + br[3];
            *(float4*)&H2N[(8 * a + ii) * 64 + 4 * b] = o;
        }
    }
    __syncthreads();                     // all X reads done
    #pragma unroll
    for (int q = 0; q < 8; q++) ((float4*)XB)[t + BT * q] = adjv[q];  // ADJ
    __syncthreads();                     // ADJ + H2N visible

    // ---- Phase 2: agg[d][c] = sum_s adj[d][s]*h2[s][c], N-packed 8x(2 ull) ----
    ull acc2[8][2] = {};
    float wc0[16];
    #pragma unroll
    for (int q = 0; q < 16; q++) wc0[q] = g_Wcat2[t + BT * q];  // prefetch Wcat chunk0
    {
        const float* ADJs = XB + gg * 4096;
        const float* H2g  = H2N + gg * 4096;
        #pragma unroll 4
        for (int si = 0; si < 16; si++) {
            int s4 = si * 4;
            float af[8][4];
            #pragma unroll
            for (int ii = 0; ii < 8; ii++) {
                float4 v = *(const float4*)&ADJs[(8 * (a & 7) + ii) * 64 + s4];
                af[ii][0] = v.x; af[ii][1] = v.y; af[ii][2] = v.z; af[ii][3] = v.w;
            }
            #pragma unroll
            for (int s2 = 0; s2 < 4; s2++) {
                ulonglong2 hv = *(const ulonglong2*)&H2g[(s4 + s2) * 64 + 4 * b];
                #pragma unroll
                for (int ii = 0; ii < 8; ii++) {
                    ull m2 = dup2(af[ii][s2]);
                    fma2(acc2[ii][0], m2, hv.x);
                    fma2(acc2[ii][1], m2, hv.y);
                }
            }
        }
    }
    __syncthreads();                     // ADJ reads done
    #pragma unroll
    for (int ii = 0; ii < 8; ii++)       // AGG overwrites ADJ region (global rows)
        *(float4*)&XB[(8 * a + ii) * 64 + 4 * b] =
            make_float4(lo32(acc2[ii][0]), hi32(acc2[ii][0]),
                        lo32(acc2[ii][1]), hi32(acc2[ii][1]));
    #pragma unroll
    for (int q = 0; q < 16; q++) WEF[t + BT * q] = wc0[q];       // Wcat buf0
    __syncthreads();

    // ---- Phase 3: out[r][j] = sum_c M[r][c]*Wcat[c][j], N-packed 8x(4 ull) ----
    ull acc3[8][4] = {};
    for (int q = 0; q < 4; q++) {
        const float* Wq = WEF + (q & 1) * 4096;
        float wn[16];
        if (q < 3) {
            #pragma unroll
            for (int r = 0; r < 16; r++) wn[r] = g_Wcat2[(q + 1) * 4096 + t + BT * r];
        }
        const float* M = (q < 2) ? XB : H2N;
        const int coff = (q & 1) * 32;
        #pragma unroll
        for (int ci = 0; ci < 8; ci++) {
            int c4 = ci * 4;
            float mf[8][4];
            #pragma unroll
            for (int ii = 0; ii < 8; ii++) {
                float4 v = *(const float4*)&M[(8 * a + ii) * 64 + coff + c4];
                mf[ii][0] = v.x; mf[ii][1] = v.y; mf[ii][2] = v.z; mf[ii][3] = v.w;
            }
            #pragma unroll
            for (int c2 = 0; c2 < 4; c2++) {
                ull wv[4];
                #pragma unroll
                for (int s = 0; s < 4; s++)
                    wv[s] = *(const ull*)&Wq[(c4 + c2) * 128 + 2 * b + 32 * s];
                #pragma unroll
                for (int ii = 0; ii < 8; ii++) {
                    ull m2 = dup2(mf[ii][c2]);
                    #pragma unroll
                    for (int s = 0; s < 4; s++) fma2(acc3[ii][s], m2, wv[s]);
                }
            }
        }
        if (q < 3) {
            float* Wn = WEF + ((q + 1) & 1) * 4096;
            #pragma unroll
            for (int r = 0; r < 16; r++) Wn[t + BT * r] = wn[r];
            __syncthreads();
        }
    }

    // ---- epilogue: bias + moments (packed lanes = separate j's) ----
    float* RED = WEF;                    // buf0: free (q=3 reads buf1/AGG/H2N only)
    #pragma unroll
    for (int s = 0; s < 4; s++) {
        ull rb = *(const ull*)&rel_b[2 * b + 32 * s];
        ull sum1 = 0ull, sum2 = 0ull;
        #pragma unroll
        for (int ii = 0; ii < 8; ii++) {
            ull v = add2(acc3[ii][s], rb);
            sum1 = add2(sum1, v);
            fma2(sum2, v, v);
        }
        int base = gg * 1024 + (a & 7) * 128 + 2 * b + 32 * s;
        *(ull*)&RED[base]        = sum1;
        *(ull*)&RED[2048 + base] = sum2;
    }
    __syncthreads();
    {
        int gg2 = t >> 7, j = t & 127;
        float S1 = 0.f, S2 = 0.f;
        #pragma unroll
        for (int ag = 0; ag < 8; ag++) {
            S1 += RED[gg2 * 1024 + ag * 128 + j];
            S2 += RED[2048 + gg2 * 1024 + ag * 128 + j];
        }
        int gl = bid * 2 + gg2;
        g_S1[gl * DHID + j] = S1;
        g_S2[gl * DHID + j] = S2;
        atomicAdd(&g_Gsum[j], S1);
        atomicAdd(&g_Gsq[j], S2);
    }
}

// ---------------------------------------------------------------------------
// Kernel 2: BN stats -> pooled moments -> log -> fc2 -> sigmoid (2 graphs/CTA)
// ---------------------------------------------------------------------------
__global__ void final_kernel(const float* __restrict__ bn_g, const float* __restrict__ bn_b,
                             const float* __restrict__ fc2_w, const float* __restrict__ fc2_b,
                             float* __restrict__ out, float invN) {
    int t = threadIdx.x;
    int h = t >> 7;
    int g = blockIdx.x * 2 + h;
    int j = t & 127;
    float mu  = g_Gsum[j] * invN;
    float var = g_Gsq[j] * invN - mu * mu;
    float aa  = bn_g[j] * rsqrtf(var + 1e-5f);
    float cc  = bn_b[j] - aa * mu;
    float s1  = g_S1[g * DHID + j];
    float s2  = g_S2[g * DHID + j];
    float pooled = (aa * aa * s2 + 2.f * aa * cc * s1) * (1.f / 64.f) + cc * cc;
    float pl = logf(fmaxf(pooled, 1e-6f));
    float p0 = pl * fc2_w[j];
    float p1 = pl * fc2_w[DHID + j];
    float p2 = pl * fc2_w[2 * DHID + j];
    #pragma unroll
    for (int off = 16; off > 0; off >>= 1) {
        p0 += __shfl_down_sync(0xffffffffu, p0, off);
        p1 += __shfl_down_sync(0xffffffffu, p1, off);
        p2 += __shfl_down_sync(0xffffffffu, p2, off);
    }
    __shared__ float r[24];
    if ((t & 31) == 0) {
        int w = t >> 5;
        r[w * 3 + 0] = p0; r[w * 3 + 1] = p1; r[w * 3 + 2] = p2;
    }
    __syncthreads();
    if (j < 3) {
        int base = h * 12;
        float v = r[base + j] + r[base + 3 + j] + r[base + 6 + j] + r[base + 9 + j] + fc2_b[j];
        out[g * 3 + j] = 1.f / (1.f + expf(-v));
    }
}

// ---------------------------------------------------------------------------
extern "C" void kernel_launch(void* const* d_in, const int* in_sizes, int n_in,
                              void* d_out, int out_size) {
    const float* x      = (const float*)d_in[0];
    const int*   ei     = (const int*)d_in[1];     // int32 (JAX x64 disabled)
    const float* conv_w = (const float*)d_in[3];
    const float* conv_b = (const float*)d_in[4];
    const float* fc1_w  = (const float*)d_in[5];
    const float* fc1_b  = (const float*)d_in[6];
    const float* rel_w  = (const float*)d_in[7];
    const float* rel_b  = (const float*)d_in[8];
    const float* root_w = (const float*)d_in[9];
    const float* bn_g   = (const float*)d_in[10];
    const float* bn_b   = (const float*)d_in[11];
    const float* fc2_w  = (const float*)d_in[12];
    const float* fc2_b  = (const float*)d_in[13];
    float* out = (float*)d_out;

    const int Ntot = in_sizes[0] / TD;     // 32768
    const int G    = Ntot / NPG;           // 512
    const int Etot = in_sizes[1] / 2;      // 1048576

    const int smem_bytes = 24576 * 4;      // 96KB
    cudaFuncSetAttribute(graph_kernel, cudaFuncAttributeMaxDynamicSharedMemorySize, smem_bytes);

    setup_kernel<<<512, BT>>>(conv_w, conv_b, fc1_w, fc1_b, rel_w, root_w, ei, Etot);
    graph_kernel<<<G / 2, BT, smem_bytes>>>(x, rel_b);
    final_kernel<<<G / 2, BT>>>(bn_g, bn_b, fc2_w, fc2_b, out, 1.0f / (float)Ntot);
}